// round 1
// baseline (speedup 1.0000x reference)
#include <cuda_runtime.h>
#include <cstdint>

// Integrator: y[b,c,n] = cumsum over time axis. 32 independent rows, T = 2^20.
// Single-pass tile scan with a published-aggregate spine (deterministic:
// every tile sums ALL predecessor aggregates with a fixed grouping).

#define THREADS 256
#define ITEMS 8
#define TILE (THREADS * ITEMS)          // 2048
#define T_LEN 1048576
#define TILES_PER_ROW (T_LEN / TILE)    // 512 (power of two)
#define MAX_TILES 16384                 // 32 rows * 512

// Spine: flag (hi 32) | float bits (lo 32). flag: 0 = invalid, 1 = aggregate.
__device__ unsigned long long g_spine[MAX_TILES];

__global__ void integrator_init_kernel(int ntiles) {
    int i = blockIdx.x * blockDim.x + threadIdx.x;
    if (i < ntiles) g_spine[i] = 0ULL;
}

__device__ __forceinline__ unsigned long long pack_agg(float v) {
    return (1ULL << 32) | (unsigned long long)__float_as_uint(v);
}

__device__ __forceinline__ void spine_publish(unsigned long long* p, unsigned long long v) {
    asm volatile("st.global.relaxed.gpu.b64 [%0], %1;" :: "l"(p), "l"(v) : "memory");
}

__device__ __forceinline__ unsigned long long spine_poll(const unsigned long long* p) {
    unsigned long long v;
    asm volatile("ld.global.relaxed.gpu.b64 %0, [%1];" : "=l"(v) : "l"(p) : "memory");
    return v;
}

__global__ __launch_bounds__(THREADS, 8)
void integrator_scan_kernel(const float* __restrict__ x, float* __restrict__ y) {
    __shared__ float s_warp[8];      // warp inclusive totals
    __shared__ float s_woff[8];      // exclusive warp offsets within tile
    __shared__ float s_excl;         // exclusive prefix of this tile within its row

    const int bid = blockIdx.x;
    const int tile_in_row = bid & (TILES_PER_ROW - 1);
    const long long base = (long long)bid * TILE;

    const int t = threadIdx.x;
    const int lane = t & 31;
    const int warp = t >> 5;

    // ---- load 8 contiguous items per thread (two float4, 16B sectors exact) ----
    const float4* xv = reinterpret_cast<const float4*>(x + base);
    float4 a = xv[t * 2];
    float4 b = xv[t * 2 + 1];

    // thread-local inclusive scan
    float r0 = a.x;
    float r1 = r0 + a.y;
    float r2 = r1 + a.z;
    float r3 = r2 + a.w;
    float r4 = r3 + b.x;
    float r5 = r4 + b.y;
    float r6 = r5 + b.z;
    float r7 = r6 + b.w;
    const float tot = r7;

    // warp inclusive scan of per-thread totals
    float incl = tot;
    #pragma unroll
    for (int d = 1; d < 32; d <<= 1) {
        float n = __shfl_up_sync(0xffffffffu, incl, d);
        if (lane >= d) incl += n;
    }
    if (lane == 31) s_warp[warp] = incl;
    const float thr_excl = incl - tot;   // exclusive offset within warp

    __syncthreads();

    if (warp == 0) {
        // scan the 8 warp totals
        float w = (lane < 8) ? s_warp[lane] : 0.0f;
        float wincl = w;
        #pragma unroll
        for (int d = 1; d < 8; d <<= 1) {
            float n = __shfl_up_sync(0xffffffffu, wincl, d);
            if (lane >= d) wincl += n;
        }
        if (lane < 8) s_woff[lane] = wincl - w;
        const float blocktot = __shfl_sync(0xffffffffu, wincl, 7);

        // publish this tile's aggregate ASAP (single 64-bit word: no fence needed)
        if (lane == 0) spine_publish(&g_spine[bid], pack_agg(blocktot));

        // deterministic spine accumulation: sum ALL predecessor aggregates.
        // lane l owns tiles {l, l+32, l+64, ...} < tile_in_row (fixed grouping).
        float excl = 0.0f;
        if (tile_in_row > 0) {
            const int rowbase = bid - tile_in_row;
            float lsum = 0.0f;
            for (int p = lane; p < tile_in_row; p += 32) {
                unsigned long long v;
                do {
                    v = spine_poll(&g_spine[rowbase + p]);
                } while ((unsigned)(v >> 32) == 0u);
                lsum += __uint_as_float((unsigned)v);
            }
            #pragma unroll
            for (int d = 16; d; d >>= 1)
                lsum += __shfl_xor_sync(0xffffffffu, lsum, d);
            excl = lsum;
        }
        if (lane == 0) s_excl = excl;
    }

    __syncthreads();

    const float off = s_excl + s_woff[warp] + thr_excl;

    float4 o0 = make_float4(off + r0, off + r1, off + r2, off + r3);
    float4 o1 = make_float4(off + r4, off + r5, off + r6, off + r7);
    float4* yv = reinterpret_cast<float4*>(y + base);
    yv[t * 2]     = o0;
    yv[t * 2 + 1] = o1;
}

extern "C" void kernel_launch(void* const* d_in, const int* in_sizes, int n_in,
                              void* d_out, int out_size) {
    const float* x = (const float*)d_in[0];
    float* y = (float*)d_out;

    const int n = out_size;              // 8*4*1048576 = 33554432
    const int ntiles = n / TILE;         // 16384

    integrator_init_kernel<<<(ntiles + 255) / 256, 256>>>(ntiles);
    integrator_scan_kernel<<<ntiles, THREADS>>>(x, y);
}

// round 2
// speedup vs baseline: 1.0240x; 1.0240x over previous
#include <cuda_runtime.h>
#include <cstdint>

// Integrator: y[b,c,n] = cumsum over time axis. 32 independent rows, T = 2^20.
// Single-pass tile scan with a published-aggregate spine (deterministic:
// every tile sums ALL predecessor aggregates with a fixed grouping).
//
// R2 changes: TILE 2048->4096 (8 spine entries/lane max), MLP'd batched
// polling (loads issued in parallel per round), streaming cache hints.

#define THREADS 256
#define ITEMS 16
#define TILE (THREADS * ITEMS)          // 4096
#define T_LEN 1048576
#define TILES_PER_ROW (T_LEN / TILE)    // 256 (power of two)
#define MAX_TILES 8192                  // 32 rows * 256

// Spine: flag (hi 32) | float bits (lo 32). flag: 0 = invalid, 1 = aggregate.
__device__ unsigned long long g_spine[MAX_TILES];

__global__ void integrator_init_kernel(int ntiles) {
    int i = blockIdx.x * blockDim.x + threadIdx.x;
    if (i < ntiles) g_spine[i] = 0ULL;
}

__device__ __forceinline__ unsigned long long pack_agg(float v) {
    return (1ULL << 32) | (unsigned long long)__float_as_uint(v);
}

__device__ __forceinline__ void spine_publish(unsigned long long* p, unsigned long long v) {
    asm volatile("st.global.relaxed.gpu.b64 [%0], %1;" :: "l"(p), "l"(v) : "memory");
}

__device__ __forceinline__ unsigned long long spine_poll(const unsigned long long* p) {
    unsigned long long v;
    asm volatile("ld.global.relaxed.gpu.b64 %0, [%1];" : "=l"(v) : "l"(p) : "memory");
    return v;
}

__global__ __launch_bounds__(THREADS, 6)
void integrator_scan_kernel(const float* __restrict__ x, float* __restrict__ y) {
    __shared__ float s_warp[8];      // warp inclusive totals
    __shared__ float s_woff[8];      // exclusive warp offsets within tile
    __shared__ float s_excl;         // exclusive prefix of this tile within its row

    const int bid = blockIdx.x;
    const int tile_in_row = bid & (TILES_PER_ROW - 1);
    const long long base = (long long)bid * TILE;

    const int t = threadIdx.x;
    const int lane = t & 31;
    const int warp = t >> 5;

    // ---- load 16 contiguous items per thread (four float4), streaming ----
    const float4* xv = reinterpret_cast<const float4*>(x + base);
    float4 a0 = __ldcs(xv + t * 4 + 0);
    float4 a1 = __ldcs(xv + t * 4 + 1);
    float4 a2 = __ldcs(xv + t * 4 + 2);
    float4 a3 = __ldcs(xv + t * 4 + 3);

    // thread-local inclusive scan (in place)
    a0.y += a0.x; a0.z += a0.y; a0.w += a0.z;
    a1.x += a0.w; a1.y += a1.x; a1.z += a1.y; a1.w += a1.z;
    a2.x += a1.w; a2.y += a2.x; a2.z += a2.y; a2.w += a2.z;
    a3.x += a2.w; a3.y += a3.x; a3.z += a3.y; a3.w += a3.z;
    const float tot = a3.w;

    // warp inclusive scan of per-thread totals
    float incl = tot;
    #pragma unroll
    for (int d = 1; d < 32; d <<= 1) {
        float n = __shfl_up_sync(0xffffffffu, incl, d);
        if (lane >= d) incl += n;
    }
    if (lane == 31) s_warp[warp] = incl;
    const float thr_excl = incl - tot;   // exclusive offset within warp

    __syncthreads();

    if (warp == 0) {
        // scan the 8 warp totals
        float w = (lane < 8) ? s_warp[lane] : 0.0f;
        float wincl = w;
        #pragma unroll
        for (int d = 1; d < 8; d <<= 1) {
            float n = __shfl_up_sync(0xffffffffu, wincl, d);
            if (lane >= d) wincl += n;
        }
        if (lane < 8) s_woff[lane] = wincl - w;
        const float blocktot = __shfl_sync(0xffffffffu, wincl, 7);

        // publish this tile's aggregate ASAP (single 64-bit word: no fence needed)
        if (lane == 0) spine_publish(&g_spine[bid], pack_agg(blocktot));

        // Deterministic spine accumulation: sum ALL predecessor aggregates.
        // lane l owns tiles {l, l+32, ..} < tile_in_row (<=8 entries each).
        // Polling is batched: all still-pending loads of a round are issued
        // back-to-back (MLP), flags checked afterwards.
        float excl = 0.0f;
        if (tile_in_row > 0) {
            const int rowbase = bid - tile_in_row;
            const int cnt = (tile_in_row > lane) ? ((tile_in_row - lane + 31) >> 5) : 0;
            float v[8];
            unsigned pend = (cnt > 0) ? ((1u << cnt) - 1u) : 0u;
            while (pend) {
                unsigned long long w8[8];
                #pragma unroll
                for (int i = 0; i < 8; i++)
                    if (pend & (1u << i))
                        w8[i] = spine_poll(&g_spine[rowbase + lane + 32 * i]);
                #pragma unroll
                for (int i = 0; i < 8; i++)
                    if ((pend & (1u << i)) && (unsigned)(w8[i] >> 32)) {
                        v[i] = __uint_as_float((unsigned)w8[i]);
                        pend &= ~(1u << i);
                    }
            }
            float lsum = 0.0f;
            #pragma unroll
            for (int i = 0; i < 8; i++)
                if (i < cnt) lsum += v[i];
            #pragma unroll
            for (int d = 16; d; d >>= 1)
                lsum += __shfl_xor_sync(0xffffffffu, lsum, d);
            excl = lsum;
        }
        if (lane == 0) s_excl = excl;
    }

    __syncthreads();

    const float off = s_excl + s_woff[warp] + thr_excl;

    float4* yv = reinterpret_cast<float4*>(y + base);
    a0.x += off; a0.y += off; a0.z += off; a0.w += off;
    a1.x += off; a1.y += off; a1.z += off; a1.w += off;
    a2.x += off; a2.y += off; a2.z += off; a2.w += off;
    a3.x += off; a3.y += off; a3.z += off; a3.w += off;
    __stcs(yv + t * 4 + 0, a0);
    __stcs(yv + t * 4 + 1, a1);
    __stcs(yv + t * 4 + 2, a2);
    __stcs(yv + t * 4 + 3, a3);
}

extern "C" void kernel_launch(void* const* d_in, const int* in_sizes, int n_in,
                              void* d_out, int out_size) {
    const float* x = (const float*)d_in[0];
    float* y = (float*)d_out;

    const int n = out_size;              // 8*4*1048576 = 33554432
    const int ntiles = n / TILE;         // 8192

    integrator_init_kernel<<<(ntiles + 255) / 256, 256>>>(ntiles);
    integrator_scan_kernel<<<ntiles, THREADS>>>(x, y);
}